// round 1
// baseline (speedup 1.0000x reference)
#include <cuda_runtime.h>
#include <cuda_bf16.h>
#include <math_constants.h>

// Problem constants
#define NTOK 8192
#define DIM  1024
#define DK   128
#define DV   128

// Scratch for projections (device globals: allocation-free)
__device__ float g_qk[NTOK * DK];
__device__ float g_v[NTOK * DV];

// ---------------------------------------------------------------------------
// Projection kernel: out[n, c] = sum_d x[n,d] * W[c,d] + b[c]
// Block computes 64 rows x 128 cols. blockIdx.y selects (Wqk,bqk)->g_qk or (Wv,bv)->g_v.
// ---------------------------------------------------------------------------
__global__ __launch_bounds__(256, 2)
void proj_kernel(const float* __restrict__ x,
                 const float* __restrict__ Wqk, const float* __restrict__ bqk,
                 const float* __restrict__ Wv,  const float* __restrict__ bv) {
    const int row0 = blockIdx.x * 64;
    const float* W;  const float* bias;  float* out;
    if (blockIdx.y == 0) { W = Wqk; bias = bqk; out = g_qk; }
    else                 { W = Wv;  bias = bv;  out = g_v;  }

    __shared__ float sxT[32][68];    // [k][row]  64 rows
    __shared__ float swT[32][132];   // [k][col] 128 cols

    const int tid = threadIdx.x;
    const int tx = tid & 15;         // col group: cols tx*8 .. tx*8+7
    const int ty = tid >> 4;         // row group: rows ty*4 .. ty*4+3

    float acc[4][8];
#pragma unroll
    for (int i = 0; i < 4; i++)
#pragma unroll
        for (int j = 0; j < 8; j++) acc[i][j] = 0.f;

    for (int kk = 0; kk < DIM; kk += 32) {
        __syncthreads();
        // x tile -> transposed smem (lanes vary row -> conflict-free STS)
#pragma unroll
        for (int it = 0; it < 2; it++) {
            int idx = it * 256 + tid;
            int r = idx & 63, kq = idx >> 6;            // kq in 0..7
            float4 g = *(const float4*)&x[(size_t)(row0 + r) * DIM + kk + kq * 4];
            sxT[kq * 4 + 0][r] = g.x; sxT[kq * 4 + 1][r] = g.y;
            sxT[kq * 4 + 2][r] = g.z; sxT[kq * 4 + 3][r] = g.w;
        }
        // W tile -> transposed smem
#pragma unroll
        for (int it = 0; it < 4; it++) {
            int idx = it * 256 + tid;
            int c = idx & 127, kq = idx >> 7;           // kq in 0..7
            float4 g = *(const float4*)&W[(size_t)c * DIM + kk + kq * 4];
            swT[kq * 4 + 0][c] = g.x; swT[kq * 4 + 1][c] = g.y;
            swT[kq * 4 + 2][c] = g.z; swT[kq * 4 + 3][c] = g.w;
        }
        __syncthreads();

#pragma unroll 8
        for (int k = 0; k < 32; k++) {
            const float4 a = *(const float4*)&sxT[k][ty << 2];
            const float4 b0 = *(const float4*)&swT[k][tx << 3];
            const float4 b1 = *(const float4*)&swT[k][(tx << 3) + 4];
            const float av[4] = {a.x, a.y, a.z, a.w};
            const float bv8[8] = {b0.x, b0.y, b0.z, b0.w, b1.x, b1.y, b1.z, b1.w};
#pragma unroll
            for (int i = 0; i < 4; i++)
#pragma unroll
                for (int j = 0; j < 8; j++) acc[i][j] += av[i] * bv8[j];
        }
    }

    // epilogue with bias
    float bb[8];
#pragma unroll
    for (int j = 0; j < 8; j++) bb[j] = bias[(tx << 3) + j];
#pragma unroll
    for (int i = 0; i < 4; i++) {
        int r = row0 + (ty << 2) + i;
        float4 o0 = make_float4(acc[i][0] + bb[0], acc[i][1] + bb[1], acc[i][2] + bb[2], acc[i][3] + bb[3]);
        float4 o1 = make_float4(acc[i][4] + bb[4], acc[i][5] + bb[5], acc[i][6] + bb[6], acc[i][7] + bb[7]);
        *(float4*)&out[(size_t)r * DK + (tx << 3)]     = o0;
        *(float4*)&out[(size_t)r * DK + (tx << 3) + 4] = o1;
    }
}

// ---------------------------------------------------------------------------
// Flash attention kernel: Q = K = g_qk, V = g_v. BM=64 rows per block, BN=64 keys/tile.
// smem layout (dynamic):
//   Qt [128][68]  transposed Q tile
//   Kt [128][68]  transposed K tile
//   Vs [64][132]  row-major V tile
//   Ps [64][65]   probabilities
// ---------------------------------------------------------------------------
#define QT_LD 68
#define VS_LD 132
#define PS_LD 65
#define SM_QT 0
#define SM_KT (SM_QT + 128 * QT_LD)
#define SM_VS (SM_KT + 128 * QT_LD)
#define SM_PS (SM_VS + 64 * VS_LD)
#define FLASH_SMEM ((SM_PS + 64 * PS_LD) * sizeof(float))

__global__ __launch_bounds__(256, 1)
void flash_kernel(float* __restrict__ out) {
    extern __shared__ float sm[];
    float* Qt = sm + SM_QT;
    float* Kt = sm + SM_KT;
    float* Vs = sm + SM_VS;
    float* Ps = sm + SM_PS;

    const int row0 = blockIdx.x * 64;
    const int tid = threadIdx.x;
    const int tx = tid & 15;    // key-col group (4 cols) / out-col group (8 cols)
    const int ty = tid >> 4;    // row group (4 rows)

    // Load Q tile transposed (once). Lanes vary row -> conflict-free STS.
#pragma unroll
    for (int it = 0; it < 8; it++) {
        int idx = it * 256 + tid;
        int r = idx & 63, kq = idx >> 6;                // kq 0..31
        float4 g = *(const float4*)&g_qk[(size_t)(row0 + r) * DK + kq * 4];
        Qt[(kq * 4 + 0) * QT_LD + r] = g.x; Qt[(kq * 4 + 1) * QT_LD + r] = g.y;
        Qt[(kq * 4 + 2) * QT_LD + r] = g.z; Qt[(kq * 4 + 3) * QT_LD + r] = g.w;
    }

    float m[4], l[4], o[4][8];
#pragma unroll
    for (int i = 0; i < 4; i++) {
        m[i] = -CUDART_INF_F; l[i] = 0.f;
#pragma unroll
        for (int d = 0; d < 8; d++) o[i][d] = 0.f;
    }

    for (int j0 = 0; j0 < NTOK; j0 += 64) {
        __syncthreads();
        // K tile transposed
#pragma unroll
        for (int it = 0; it < 8; it++) {
            int idx = it * 256 + tid;
            int r = idx & 63, kq = idx >> 6;
            float4 g = *(const float4*)&g_qk[(size_t)(j0 + r) * DK + kq * 4];
            Kt[(kq * 4 + 0) * QT_LD + r] = g.x; Kt[(kq * 4 + 1) * QT_LD + r] = g.y;
            Kt[(kq * 4 + 2) * QT_LD + r] = g.z; Kt[(kq * 4 + 3) * QT_LD + r] = g.w;
        }
        // V tile row-major (coalesced both sides)
#pragma unroll
        for (int it = 0; it < 8; it++) {
            int idx = it * 256 + tid;
            int jr = idx >> 5, kq = idx & 31;
            float4 g = *(const float4*)&g_v[(size_t)(j0 + jr) * DV + kq * 4];
            *(float4*)&Vs[jr * VS_LD + kq * 4] = g;
        }
        __syncthreads();

        // S = Q K^T  (4x4 per thread)
        float s[4][4];
#pragma unroll
        for (int i = 0; i < 4; i++)
#pragma unroll
            for (int j = 0; j < 4; j++) s[i][j] = 0.f;

#pragma unroll 8
        for (int k = 0; k < 128; k++) {
            const float4 a = *(const float4*)&Qt[k * QT_LD + (ty << 2)];
            const float4 b = *(const float4*)&Kt[k * QT_LD + (tx << 2)];
            const float av[4] = {a.x, a.y, a.z, a.w};
            const float bv4[4] = {b.x, b.y, b.z, b.w};
#pragma unroll
            for (int i = 0; i < 4; i++)
#pragma unroll
                for (int j = 0; j < 4; j++) s[i][j] += av[i] * bv4[j];
        }

        // Online softmax (row reductions across 16 lanes of same ty, width-16 shuffles)
#pragma unroll
        for (int i = 0; i < 4; i++) {
            float tmax = fmaxf(fmaxf(s[i][0], s[i][1]), fmaxf(s[i][2], s[i][3]));
#pragma unroll
            for (int off = 8; off >= 1; off >>= 1)
                tmax = fmaxf(tmax, __shfl_xor_sync(0xffffffffu, tmax, off, 16));
            const float newm = fmaxf(m[i], tmax);
            const float alpha = __expf(m[i] - newm);
            float psum = 0.f;
            const int prow = ((ty << 2) + i) * PS_LD;
#pragma unroll
            for (int j = 0; j < 4; j++) {
                float p = __expf(s[i][j] - newm);
                Ps[prow + (tx << 2) + j] = p;
                psum += p;
            }
#pragma unroll
            for (int off = 8; off >= 1; off >>= 1)
                psum += __shfl_xor_sync(0xffffffffu, psum, off, 16);
            l[i] = l[i] * alpha + psum;
            m[i] = newm;
#pragma unroll
            for (int d = 0; d < 8; d++) o[i][d] *= alpha;
        }
        __syncwarp();   // Ps rows are produced & consumed within one warp

        // O += P * V
#pragma unroll 2
        for (int j = 0; j < 64; j++) {
            const float4 v0 = *(const float4*)&Vs[j * VS_LD + (tx << 3)];
            const float4 v1 = *(const float4*)&Vs[j * VS_LD + (tx << 3) + 4];
#pragma unroll
            for (int i = 0; i < 4; i++) {
                const float p = Ps[((ty << 2) + i) * PS_LD + j];
                o[i][0] += p * v0.x; o[i][1] += p * v0.y;
                o[i][2] += p * v0.z; o[i][3] += p * v0.w;
                o[i][4] += p * v1.x; o[i][5] += p * v1.y;
                o[i][6] += p * v1.z; o[i][7] += p * v1.w;
            }
        }
    }

    // Epilogue: normalize and store
#pragma unroll
    for (int i = 0; i < 4; i++) {
        const float inv = 1.f / l[i];
        const int r = row0 + (ty << 2) + i;
        float4 o0 = make_float4(o[i][0] * inv, o[i][1] * inv, o[i][2] * inv, o[i][3] * inv);
        float4 o1 = make_float4(o[i][4] * inv, o[i][5] * inv, o[i][6] * inv, o[i][7] * inv);
        *(float4*)&out[(size_t)r * DV + (tx << 3)]     = o0;
        *(float4*)&out[(size_t)r * DV + (tx << 3) + 4] = o1;
    }
}

// ---------------------------------------------------------------------------
extern "C" void kernel_launch(void* const* d_in, const int* in_sizes, int n_in,
                              void* d_out, int out_size) {
    const float* x   = (const float*)d_in[0];
    const float* Wqk = (const float*)d_in[1];
    const float* bqk = (const float*)d_in[2];
    const float* Wv  = (const float*)d_in[3];
    const float* bv  = (const float*)d_in[4];
    float* out = (float*)d_out;

    cudaFuncSetAttribute(flash_kernel, cudaFuncAttributeMaxDynamicSharedMemorySize,
                         (int)FLASH_SMEM);

    proj_kernel<<<dim3(NTOK / 64, 2), 256>>>(x, Wqk, bqk, Wv, bv);
    flash_kernel<<<NTOK / 64, 256, FLASH_SMEM>>>(out);
}